// round 9
// baseline (speedup 1.0000x reference)
#include <cuda_runtime.h>
#include <cuda_fp16.h>
#include <math.h>

#define NF 2048

// ---------------- scratch (device globals: no allocations allowed) ----------
__device__ float g_pool1[NF * 64 * 8 * 14];   // 58.7 MB
__device__ float g_feats[NF * 1920];          // 15.7 MB
__device__ float g_xproj[NF * 5760];          // 47.2 MB
__device__ __half g_whh_h[5760 * 1920];       // 22.1 MB, [unit][gate][k]
__device__ uint2 g_msg[NF + 1][1920];         // per-unit {tag, h}, 31.5 MB

// un-hoistable L2 8B load / store (single-instr, un-torn)
__device__ __forceinline__ uint2 ld_cg_u2(const uint2* p) {
    uint2 v;
    asm volatile("ld.global.cg.v2.u32 {%0,%1}, [%2];"
                 : "=r"(v.x), "=r"(v.y) : "l"(p) : "memory");
    return v;
}
__device__ __forceinline__ void st_cg_u2(uint2* p, uint2 v) {
    asm volatile("st.global.cg.v2.u32 [%0], {%1,%2};"
                 :: "l"(p), "r"(v.x), "r"(v.y) : "memory");
}

// ---------------- conv1 (9x9, pad2) + sigmoid + pool3 ----------------------
#define C1_P 1600
#define C1_W 1296
#define C1_CB 16128
#define C1_SMEM ((C1_P + C1_W + C1_CB) * 4)

__global__ void conv1_kernel(const float* __restrict__ x,
                             const float* __restrict__ w,
                             const float* __restrict__ b) {
    extern __shared__ float sm[];
    float* P  = sm;
    float* W  = sm + C1_P;
    float* CB = sm + C1_P + C1_W;
    __shared__ float sb[16];
    const int n = blockIdx.x, c0 = blockIdx.y * 16;
    const int tid = threadIdx.x;

    for (int i = tid; i < C1_P; i += 256) P[i] = 0.f;
    for (int i = tid; i < C1_W; i += 256) W[i] = w[c0 * 81 + i];
    if (tid < 16) sb[tid] = b[c0 + tid];
    __syncthreads();
    for (int i = tid; i < 28 * 46; i += 256) {
        int r = i / 46, c = i % 46;
        P[(r + 2) * 50 + (c + 2)] = x[n * 1288 + i];
    }
    __syncthreads();

    for (int task = tid; task < 2688; task += 256) {
        int c = task / 168, rem = task % 168;
        int i = rem / 7, j0 = (rem % 7) * 6;
        float acc[6] = {0.f, 0.f, 0.f, 0.f, 0.f, 0.f};
        const float* wc = W + c * 81;
        #pragma unroll
        for (int ky = 0; ky < 9; ky++) {
            const float* pr = P + (i + ky) * 50 + j0;
            float xv[14];
            #pragma unroll
            for (int u = 0; u < 14; u++) xv[u] = pr[u];
            #pragma unroll
            for (int kx = 0; kx < 9; kx++) {
                float wv = wc[ky * 9 + kx];
                #pragma unroll
                for (int jj = 0; jj < 6; jj++)
                    acc[jj] = fmaf(xv[kx + jj], wv, acc[jj]);
            }
        }
        float bb = sb[c];
        #pragma unroll
        for (int jj = 0; jj < 6; jj++)
            CB[(c * 24 + i) * 42 + j0 + jj] = 1.f / (1.f + expf(-(acc[jj] + bb)));
    }
    __syncthreads();

    for (int task = tid; task < 1792; task += 256) {
        int c = task / 112, rem = task % 112;
        int py = rem / 14, px = rem % 14;
        float m = -3.4e38f;
        #pragma unroll
        for (int dy = 0; dy < 3; dy++)
            #pragma unroll
            for (int dx = 0; dx < 3; dx++)
                m = fmaxf(m, CB[(c * 24 + 3 * py + dy) * 42 + 3 * px + dx]);
        g_pool1[((n * 64 + c0 + c) * 8 + py) * 14 + px] = m;
    }
}

// ---------------- conv2 (4x4, pad2) + sigmoid + pool3, register-blocked ----
#define C2_P 13856
#define C2_CB (128 * 9 * 15)
#define C2_SMEM ((C2_P + C2_CB) * 4)

__global__ void __launch_bounds__(768, 1) conv2_kernel(const float* __restrict__ w,
                                                       const float* __restrict__ b) {
    extern __shared__ float sm[];
    float* P  = sm;
    float* CB = sm + C2_P;
    const int n = blockIdx.x;
    const int tid = threadIdx.x;
    const int NT = 768;

    for (int i = tid; i < C2_P; i += NT) P[i] = 0.f;
    __syncthreads();
    for (int i = tid; i < 7168; i += NT) {
        int ic = i / 112, rem = i % 112;
        int r = rem / 14, c = rem % 14;
        P[(ic * 12 + r + 2) * 18 + (c + 2)] = g_pool1[n * 7168 + i];
    }
    __syncthreads();

    const int jh = tid & 1;
    const int rg = (tid >> 1) % 3;
    const int oc = tid / 6;
    const int j0 = jh * 8;
    const int nj = jh ? 7 : 8;
    float acc[3][8];
    #pragma unroll
    for (int i = 0; i < 3; i++)
        #pragma unroll
        for (int j = 0; j < 8; j++) acc[i][j] = 0.f;

    const float4* wb4 = (const float4*)(w + (size_t)oc * 1024);
    const float* Pb0 = P + (rg * 3) * 18 + j0;

    for (int ic = 0; ic < 64; ic++) {
        float wv[16];
        {
            float4 w0 = __ldg(wb4 + ic * 4 + 0);
            float4 w1 = __ldg(wb4 + ic * 4 + 1);
            float4 w2 = __ldg(wb4 + ic * 4 + 2);
            float4 w3 = __ldg(wb4 + ic * 4 + 3);
            wv[0] = w0.x; wv[1] = w0.y; wv[2] = w0.z; wv[3] = w0.w;
            wv[4] = w1.x; wv[5] = w1.y; wv[6] = w1.z; wv[7] = w1.w;
            wv[8] = w2.x; wv[9] = w2.y; wv[10] = w2.z; wv[11] = w2.w;
            wv[12] = w3.x; wv[13] = w3.y; wv[14] = w3.z; wv[15] = w3.w;
        }
        const float* Pb = Pb0 + ic * 12 * 18;
        #pragma unroll
        for (int ir = 0; ir < 6; ir++) {
            float xv[11];
            #pragma unroll
            for (int u = 0; u < 11; u++) xv[u] = Pb[ir * 18 + u];
            #pragma unroll
            for (int rl = 0; rl < 3; rl++) {
                const int ky = ir - rl;
                if (ky >= 0 && ky <= 3) {
                    #pragma unroll
                    for (int kx = 0; kx < 4; kx++) {
                        float wvv = wv[ky * 4 + kx];
                        #pragma unroll
                        for (int jj = 0; jj < 8; jj++)
                            acc[rl][jj] = fmaf(xv[kx + jj], wvv, acc[rl][jj]);
                    }
                }
            }
        }
    }
    {
        float bb = __ldg(b + oc);
        #pragma unroll
        for (int rl = 0; rl < 3; rl++) {
            int r = rg * 3 + rl;
            for (int jj = 0; jj < nj; jj++)
                CB[(oc * 9 + r) * 15 + j0 + jj] =
                    1.f / (1.f + expf(-(acc[rl][jj] + bb)));
        }
    }
    __syncthreads();

    for (int task = tid; task < 1920; task += NT) {
        int oc2 = task / 15, rem = task % 15;
        int py = rem / 5, px = rem % 5;
        float m = -3.4e38f;
        #pragma unroll
        for (int dy = 0; dy < 3; dy++)
            #pragma unroll
            for (int dx = 0; dx < 3; dx++)
                m = fmaxf(m, CB[(oc2 * 9 + 3 * py + dy) * 15 + 3 * px + dx]);
        g_feats[n * 1920 + oc2 * 15 + py * 5 + px] = m;
    }
}

// ---------------- x_proj GEMM: [2048,1920] x [5760,1920]^T + b_ih ----------
__global__ void __launch_bounds__(256) gemm_xproj(const float* __restrict__ W,
                                                  const float* __restrict__ bias) {
    __shared__ __align__(16) float Ast[8][128];
    __shared__ __align__(16) float Bst[8][128];
    const int m0 = blockIdx.x * 128, n0 = blockIdx.y * 128;
    const int tid = threadIdx.x;
    const int lrow = tid >> 1, lkq = tid & 1;
    const int ty = tid >> 4, tx = tid & 15;
    float acc[8][8];
    #pragma unroll
    for (int i = 0; i < 8; i++)
        #pragma unroll
        for (int j = 0; j < 8; j++) acc[i][j] = 0.f;

    const float* Ap = g_feats + (size_t)(m0 + lrow) * 1920 + lkq * 4;
    const float* Bp = W + (size_t)(n0 + lrow) * 1920 + lkq * 4;

    for (int k0 = 0; k0 < 1920; k0 += 8) {
        float4 av = *(const float4*)(Ap + k0);
        float4 bv = *(const float4*)(Bp + k0);
        __syncthreads();
        Ast[lkq * 4 + 0][lrow] = av.x; Ast[lkq * 4 + 1][lrow] = av.y;
        Ast[lkq * 4 + 2][lrow] = av.z; Ast[lkq * 4 + 3][lrow] = av.w;
        Bst[lkq * 4 + 0][lrow] = bv.x; Bst[lkq * 4 + 1][lrow] = bv.y;
        Bst[lkq * 4 + 2][lrow] = bv.z; Bst[lkq * 4 + 3][lrow] = bv.w;
        __syncthreads();
        #pragma unroll
        for (int kk = 0; kk < 8; kk++) {
            float4 a0 = *(const float4*)&Ast[kk][ty * 8];
            float4 a1 = *(const float4*)&Ast[kk][ty * 8 + 4];
            float4 b0 = *(const float4*)&Bst[kk][tx * 8];
            float4 b1 = *(const float4*)&Bst[kk][tx * 8 + 4];
            float ar[8] = {a0.x, a0.y, a0.z, a0.w, a1.x, a1.y, a1.z, a1.w};
            float br[8] = {b0.x, b0.y, b0.z, b0.w, b1.x, b1.y, b1.z, b1.w};
            #pragma unroll
            for (int i = 0; i < 8; i++)
                #pragma unroll
                for (int j = 0; j < 8; j++)
                    acc[i][j] = fmaf(ar[i], br[j], acc[i][j]);
        }
    }
    #pragma unroll
    for (int i = 0; i < 8; i++) {
        int row = m0 + ty * 8 + i;
        #pragma unroll
        for (int j = 0; j < 8; j++) {
            int col = n0 + tx * 8 + j;
            g_xproj[(size_t)row * 5760 + col] = acc[i][j] + __ldg(bias + col);
        }
    }
}

// ---------------- convert w_hh fp32 -> fp16, regrouped [unit][gate][k] -----
__global__ void convert_whh(const float* __restrict__ Whh) {
    const int row = blockIdx.x;              // 0..5759 = gate*1920 + unit
    const int gate = row / 1920, unit = row % 1920;
    const float* src = Whh + (size_t)row * 1920;
    __half* dst = g_whh_h + ((size_t)unit * 3 + gate) * 1920;
    for (int k = threadIdx.x; k < 1920; k += 256)
        dst[k] = __float2half(src[k]);
}

// ---------------- init: zero tags, publish h0 (tag=1) ----------------------
__global__ void init_kernel(const float* __restrict__ h0) {
    const int total = (NF + 1) * 1920;
    uint2* base = &g_msg[0][0];
    for (int i = blockIdx.x * blockDim.x + threadIdx.x; i < total;
         i += gridDim.x * blockDim.x) {
        uint2 v;
        if (i < 1920) { v.x = 1u; v.y = __float_as_uint(h0[i]); }
        else          { v.x = 0u; v.y = 0u; }
        st_cg_u2(base + i, v);
    }
}

// ---------------- persistent GRU scan: 148 CTAs x 13 units -----------------
// g_msg[s][u] = {tag=s+1, h[u]} fp32; per-unit messages so any unit split works.
// CTA c owns units [13c, 13c+13) clipped to 1920 (last CTA: 9 units).
#define UPC 13
#define GNT 416
#define G_WHALVES (UPC * 3 * 1920)                 // 74880 halves per CTA
#define GRU_SMEM (G_WHALVES * 2 + 1920 * 4)        // 157440 B

__global__ void __launch_bounds__(GNT) gru_kernel(const float* __restrict__ bhh) {
    extern __shared__ __align__(16) char smraw[];
    __half* sw = (__half*)smraw;
    float* sh = (float*)(smraw + G_WHALVES * 2);
    __shared__ float s_new[UPC];
    const int tid = threadIdx.x;
    const int cta = blockIdx.x;

    // stage this CTA's weight slice (clamped at array end for last CTA)
    {
        const size_t base_h = (size_t)cta * G_WHALVES;      // in halves
        const size_t total_h = 5760ull * 1920ull;
        int n16 = (int)((total_h - base_h) / 8);            // uint4 count avail
        if (n16 > G_WHALVES / 8) n16 = G_WHALVES / 8;
        const uint4* src = (const uint4*)(g_whh_h + base_h);
        uint4* dst = (uint4*)sw;
        for (int i = tid; i < n16; i += GNT) dst[i] = src[i];
    }
    const int ul = tid >> 5, lane = tid & 31;
    const int wi = cta * UPC + ul;
    const bool active = (ul < UPC) && (wi < 1920);
    const __half2* wr2 = (const __half2*)(sw + ul * 3 * 1920);
    const __half2* wz2 = wr2 + 960;
    const __half2* wn2 = wz2 + 960;
    float br = 0.f, bz = 0.f, bn = 0.f;
    if (active) { br = bhh[wi]; bz = bhh[1920 + wi]; bn = bhh[3840 + wi]; }
    __syncthreads();

    for (int t = 0; t < 2048; t++) {
        const unsigned want = (unsigned)(t + 1);

        // prefetch x-projection early (overlaps DRAM latency with the poll)
        float xr = 0.f, xz = 0.f, xn = 0.f;
        if (active && lane == 0) {
            const float* xp = g_xproj + (size_t)t * 5760;
            xr = __ldg(xp + wi); xz = __ldg(xp + 1920 + wi); xn = __ldg(xp + 3840 + wi);
        }

        // one-load detect+data: 5 interleaved poll slots (MLP=5)
        {
            uint2 v0, v1, v2, v3, v4;
            bool d0 = false, d1 = false, d2 = false, d3 = false, d4 = (tid >= 256);
            do {
                if (!d0) { v0 = ld_cg_u2(&g_msg[t][tid]);        d0 = (v0.x == want); }
                if (!d1) { v1 = ld_cg_u2(&g_msg[t][tid + 416]);  d1 = (v1.x == want); }
                if (!d2) { v2 = ld_cg_u2(&g_msg[t][tid + 832]);  d2 = (v2.x == want); }
                if (!d3) { v3 = ld_cg_u2(&g_msg[t][tid + 1248]); d3 = (v3.x == want); }
                if (!d4) { v4 = ld_cg_u2(&g_msg[t][tid + 1664]); d4 = (v4.x == want); }
            } while (!(d0 && d1 && d2 && d3 && d4));
            sh[tid]        = __uint_as_float(v0.y);
            sh[tid + 416]  = __uint_as_float(v1.y);
            sh[tid + 832]  = __uint_as_float(v2.y);
            sh[tid + 1248] = __uint_as_float(v3.y);
            if (tid < 256) sh[tid + 1664] = __uint_as_float(v4.y);
        }
        __syncthreads();

        if (active) {
            const float2* sh2 = (const float2*)sh;
            float sr = 0.f, sz = 0.f, sn = 0.f;
            #pragma unroll 6
            for (int it = 0; it < 30; it++) {
                const int idx = it * 32 + lane;
                float2 h2 = sh2[idx];
                float2 a = __half22float2(wr2[idx]);
                float2 b = __half22float2(wz2[idx]);
                float2 c = __half22float2(wn2[idx]);
                sr = fmaf(h2.y, a.y, fmaf(h2.x, a.x, sr));
                sz = fmaf(h2.y, b.y, fmaf(h2.x, b.x, sz));
                sn = fmaf(h2.y, c.y, fmaf(h2.x, c.x, sn));
            }
            #pragma unroll
            for (int off = 16; off > 0; off >>= 1) {
                sr += __shfl_xor_sync(0xffffffffu, sr, off);
                sz += __shfl_xor_sync(0xffffffffu, sz, off);
                sn += __shfl_xor_sync(0xffffffffu, sn, off);
            }
            if (lane == 0) {
                float r  = 1.f / (1.f + expf(-(xr + sr + br)));
                float z  = 1.f / (1.f + expf(-(xz + sz + bz)));
                float nn = tanhf(xn + r * (sn + bn));
                s_new[ul] = (1.f - z) * nn + z * sh[wi];
            }
        }
        __syncthreads();
        // publish this CTA's units
        if (tid < UPC) {
            int u = cta * UPC + tid;
            if (u < 1920) {
                uint2 v; v.x = want + 1u; v.y = __float_as_uint(s_new[tid]);
                st_cg_u2(&g_msg[t + 1][u], v);
            }
        }
    }
}

// ---------------- final FC: [1,1920] x [2,1920]^T + fc_b -------------------
__global__ void fc_kernel(const float* __restrict__ fcw,
                          const float* __restrict__ fcb,
                          float* __restrict__ out) {
    __shared__ float red0[256], red1[256];
    const int tid = threadIdx.x;
    float s0 = 0.f, s1 = 0.f;
    for (int k = tid; k < 1920; k += 256) {
        float hv = __uint_as_float(g_msg[NF][k].y);
        s0 = fmaf(hv, fcw[k], s0);
        s1 = fmaf(hv, fcw[1920 + k], s1);
    }
    red0[tid] = s0; red1[tid] = s1;
    __syncthreads();
    for (int s = 128; s > 0; s >>= 1) {
        if (tid < s) { red0[tid] += red0[tid + s]; red1[tid] += red1[tid + s]; }
        __syncthreads();
    }
    if (tid == 0) { out[0] = red0[0] + fcb[0]; out[1] = red1[0] + fcb[1]; }
}

// ---------------- launcher --------------------------------------------------
extern "C" void kernel_launch(void* const* d_in, const int* in_sizes, int n_in,
                              void* d_out, int out_size) {
    const float* x    = (const float*)d_in[0];
    const float* c1w  = (const float*)d_in[1];
    const float* c1b  = (const float*)d_in[2];
    const float* c2w  = (const float*)d_in[3];
    const float* c2b  = (const float*)d_in[4];
    const float* wih  = (const float*)d_in[5];
    const float* whh  = (const float*)d_in[6];
    const float* bih  = (const float*)d_in[7];
    const float* bhh  = (const float*)d_in[8];
    const float* fcw  = (const float*)d_in[9];
    const float* fcb  = (const float*)d_in[10];
    const float* h0   = (const float*)d_in[11];
    (void)in_sizes; (void)n_in; (void)out_size;

    cudaFuncSetAttribute(conv1_kernel, cudaFuncAttributeMaxDynamicSharedMemorySize, C1_SMEM);
    cudaFuncSetAttribute(conv2_kernel, cudaFuncAttributeMaxDynamicSharedMemorySize, C2_SMEM);
    cudaFuncSetAttribute(gru_kernel, cudaFuncAttributeMaxDynamicSharedMemorySize, GRU_SMEM);

    conv1_kernel<<<dim3(NF, 4), 256, C1_SMEM>>>(x, c1w, c1b);
    conv2_kernel<<<NF, 768, C2_SMEM>>>(c2w, c2b);
    gemm_xproj<<<dim3(16, 45), 256>>>(wih, bih);
    convert_whh<<<5760, 256>>>(whh);
    init_kernel<<<512, 256>>>(h0);
    gru_kernel<<<148, GNT, GRU_SMEM>>>(bhh);
    fc_kernel<<<1, 256>>>(fcw, fcb, (float*)d_out);
}

// round 12
// speedup vs baseline: 1.1903x; 1.1903x over previous
#include <cuda_runtime.h>
#include <cuda_fp16.h>
#include <math.h>

#define NF 2048

// ---------------- scratch (device globals: no allocations allowed) ----------
__device__ float g_pool1[NF * 64 * 8 * 14];   // 58.7 MB
__device__ float g_feats[NF * 1920];          // 15.7 MB
__device__ float g_xproj[NF * 5760];          // 47.2 MB
__device__ __half g_whh_h[5760 * 1920];       // 22.1 MB, [unit][gate][k]
__device__ uint4 g_msg[NF + 1][960];          // {tag,pad,h[2p],h[2p+1]}, fp32

// un-hoistable L2 16B load / store (single-instr, un-torn)
__device__ __forceinline__ uint4 ld_cg_u4(const uint4* p) {
    uint4 v;
    asm volatile("ld.global.cg.v4.u32 {%0,%1,%2,%3}, [%4];"
                 : "=r"(v.x), "=r"(v.y), "=r"(v.z), "=r"(v.w) : "l"(p) : "memory");
    return v;
}
__device__ __forceinline__ void st_cg_u4(uint4* p, uint4 v) {
    asm volatile("st.global.cg.v4.u32 [%0], {%1,%2,%3,%4};"
                 :: "l"(p), "r"(v.x), "r"(v.y), "r"(v.z), "r"(v.w) : "memory");
}

// ---------------- conv1 (9x9, pad2) + sigmoid + pool3 ----------------------
#define C1_P 1600
#define C1_W 1296
#define C1_CB 16128
#define C1_SMEM ((C1_P + C1_W + C1_CB) * 4)

__global__ void conv1_kernel(const float* __restrict__ x,
                             const float* __restrict__ w,
                             const float* __restrict__ b) {
    extern __shared__ float sm[];
    float* P  = sm;
    float* W  = sm + C1_P;
    float* CB = sm + C1_P + C1_W;
    __shared__ float sb[16];
    const int n = blockIdx.x, c0 = blockIdx.y * 16;
    const int tid = threadIdx.x;

    for (int i = tid; i < C1_P; i += 256) P[i] = 0.f;
    for (int i = tid; i < C1_W; i += 256) W[i] = w[c0 * 81 + i];
    if (tid < 16) sb[tid] = b[c0 + tid];
    __syncthreads();
    for (int i = tid; i < 28 * 46; i += 256) {
        int r = i / 46, c = i % 46;
        P[(r + 2) * 50 + (c + 2)] = x[n * 1288 + i];
    }
    __syncthreads();

    for (int task = tid; task < 2688; task += 256) {
        int c = task / 168, rem = task % 168;
        int i = rem / 7, j0 = (rem % 7) * 6;
        float acc[6] = {0.f, 0.f, 0.f, 0.f, 0.f, 0.f};
        const float* wc = W + c * 81;
        #pragma unroll
        for (int ky = 0; ky < 9; ky++) {
            const float* pr = P + (i + ky) * 50 + j0;
            float xv[14];
            #pragma unroll
            for (int u = 0; u < 14; u++) xv[u] = pr[u];
            #pragma unroll
            for (int kx = 0; kx < 9; kx++) {
                float wv = wc[ky * 9 + kx];
                #pragma unroll
                for (int jj = 0; jj < 6; jj++)
                    acc[jj] = fmaf(xv[kx + jj], wv, acc[jj]);
            }
        }
        float bb = sb[c];
        #pragma unroll
        for (int jj = 0; jj < 6; jj++)
            CB[(c * 24 + i) * 42 + j0 + jj] = 1.f / (1.f + expf(-(acc[jj] + bb)));
    }
    __syncthreads();

    for (int task = tid; task < 1792; task += 256) {
        int c = task / 112, rem = task % 112;
        int py = rem / 14, px = rem % 14;
        float m = -3.4e38f;
        #pragma unroll
        for (int dy = 0; dy < 3; dy++)
            #pragma unroll
            for (int dx = 0; dx < 3; dx++)
                m = fmaxf(m, CB[(c * 24 + 3 * py + dy) * 42 + 3 * px + dx]);
        g_pool1[((n * 64 + c0 + c) * 8 + py) * 14 + px] = m;
    }
}

// ---------------- conv2 (4x4, pad2) + sigmoid + pool3, register-blocked ----
#define C2_P 13856
#define C2_CB (128 * 9 * 15)
#define C2_SMEM ((C2_P + C2_CB) * 4)

__global__ void __launch_bounds__(768, 1) conv2_kernel(const float* __restrict__ w,
                                                       const float* __restrict__ b) {
    extern __shared__ float sm[];
    float* P  = sm;
    float* CB = sm + C2_P;
    const int n = blockIdx.x;
    const int tid = threadIdx.x;
    const int NT = 768;

    for (int i = tid; i < C2_P; i += NT) P[i] = 0.f;
    __syncthreads();
    for (int i = tid; i < 7168; i += NT) {
        int ic = i / 112, rem = i % 112;
        int r = rem / 14, c = rem % 14;
        P[(ic * 12 + r + 2) * 18 + (c + 2)] = g_pool1[n * 7168 + i];
    }
    __syncthreads();

    const int jh = tid & 1;
    const int rg = (tid >> 1) % 3;
    const int oc = tid / 6;
    const int j0 = jh * 8;
    const int nj = jh ? 7 : 8;
    float acc[3][8];
    #pragma unroll
    for (int i = 0; i < 3; i++)
        #pragma unroll
        for (int j = 0; j < 8; j++) acc[i][j] = 0.f;

    const float4* wb4 = (const float4*)(w + (size_t)oc * 1024);
    const float* Pb0 = P + (rg * 3) * 18 + j0;

    for (int ic = 0; ic < 64; ic++) {
        float wv[16];
        {
            float4 w0 = __ldg(wb4 + ic * 4 + 0);
            float4 w1 = __ldg(wb4 + ic * 4 + 1);
            float4 w2 = __ldg(wb4 + ic * 4 + 2);
            float4 w3 = __ldg(wb4 + ic * 4 + 3);
            wv[0] = w0.x; wv[1] = w0.y; wv[2] = w0.z; wv[3] = w0.w;
            wv[4] = w1.x; wv[5] = w1.y; wv[6] = w1.z; wv[7] = w1.w;
            wv[8] = w2.x; wv[9] = w2.y; wv[10] = w2.z; wv[11] = w2.w;
            wv[12] = w3.x; wv[13] = w3.y; wv[14] = w3.z; wv[15] = w3.w;
        }
        const float* Pb = Pb0 + ic * 12 * 18;
        #pragma unroll
        for (int ir = 0; ir < 6; ir++) {
            float xv[11];
            #pragma unroll
            for (int u = 0; u < 11; u++) xv[u] = Pb[ir * 18 + u];
            #pragma unroll
            for (int rl = 0; rl < 3; rl++) {
                const int ky = ir - rl;
                if (ky >= 0 && ky <= 3) {
                    #pragma unroll
                    for (int kx = 0; kx < 4; kx++) {
                        float wvv = wv[ky * 4 + kx];
                        #pragma unroll
                        for (int jj = 0; jj < 8; jj++)
                            acc[rl][jj] = fmaf(xv[kx + jj], wvv, acc[rl][jj]);
                    }
                }
            }
        }
    }
    {
        float bb = __ldg(b + oc);
        #pragma unroll
        for (int rl = 0; rl < 3; rl++) {
            int r = rg * 3 + rl;
            for (int jj = 0; jj < nj; jj++)
                CB[(oc * 9 + r) * 15 + j0 + jj] =
                    1.f / (1.f + expf(-(acc[rl][jj] + bb)));
        }
    }
    __syncthreads();

    for (int task = tid; task < 1920; task += NT) {
        int oc2 = task / 15, rem = task % 15;
        int py = rem / 5, px = rem % 5;
        float m = -3.4e38f;
        #pragma unroll
        for (int dy = 0; dy < 3; dy++)
            #pragma unroll
            for (int dx = 0; dx < 3; dx++)
                m = fmaxf(m, CB[(oc2 * 9 + 3 * py + dy) * 15 + 3 * px + dx]);
        g_feats[n * 1920 + oc2 * 15 + py * 5 + px] = m;
    }
}

// ---------------- x_proj GEMM (3xTF32 tensor cores) ------------------------
// C[2048,5760] = feats[2048,1920] @ wih[5760,1920]^T + b_ih
// split x = hi + lo (tf32 each); D = Ah*Bh + Ah*Bl + Al*Bh  (err ~1e-6 rel)
// 128x128 block tile, 8 warps x (32x64), BK=8, double-buffered smem.
#define GP 136   // smem row pad: conflict-free frag loads

__device__ __forceinline__ void tf32_split(float x, unsigned& hi, unsigned& lo) {
    unsigned h;
    asm("cvt.rna.tf32.f32 %0, %1;" : "=r"(h) : "f"(x));
    float l = x - __uint_as_float(h);
    unsigned lb;
    asm("cvt.rna.tf32.f32 %0, %1;" : "=r"(lb) : "f"(l));
    hi = h; lo = lb;
}

#define MMA_TF32(c, a, b0, b1) \
    asm volatile("mma.sync.aligned.m16n8k8.row.col.f32.tf32.tf32.f32 " \
        "{%0,%1,%2,%3}, {%4,%5,%6,%7}, {%8,%9}, {%0,%1,%2,%3};" \
        : "+f"((c)[0]), "+f"((c)[1]), "+f"((c)[2]), "+f"((c)[3]) \
        : "r"((a)[0]), "r"((a)[1]), "r"((a)[2]), "r"((a)[3]), "r"(b0), "r"(b1))

__global__ void __launch_bounds__(256) gemm_xproj_tc(const float* __restrict__ W,
                                                     const float* __restrict__ bias) {
    __shared__ unsigned sAh[2][8][GP];
    __shared__ unsigned sAl[2][8][GP];
    __shared__ unsigned sBh[2][8][GP];
    __shared__ unsigned sBl[2][8][GP];

    const int m0 = blockIdx.x * 128, n0 = blockIdx.y * 128;
    const int tid = threadIdx.x;
    const int warp = tid >> 5, lane = tid & 31;
    const int wm = warp & 3;            // 4 m-warps (32 rows each)
    const int wn = warp >> 2;           // 2 n-warps (64 cols each)
    const int gid = lane >> 2, tig = lane & 3;

    float c[2][8][4];
    #pragma unroll
    for (int i = 0; i < 2; i++)
        #pragma unroll
        for (int j = 0; j < 8; j++)
            #pragma unroll
            for (int q = 0; q < 4; q++) c[i][j][q] = 0.f;

    // producer mapping: thread t loads float4 at (row = t/2, k = (t&1)*4)
    const int pm = tid >> 1;
    const int pk = (tid & 1) * 4;
    const float* Ag = g_feats + (size_t)(m0 + pm) * 1920 + pk;
    const float* Bg = W + (size_t)(n0 + pm) * 1920 + pk;

    // stage 0
    {
        float4 ra = __ldg((const float4*)Ag);
        float4 rb = __ldg((const float4*)Bg);
        unsigned h, l;
        tf32_split(ra.x, h, l); sAh[0][pk+0][pm] = h; sAl[0][pk+0][pm] = l;
        tf32_split(ra.y, h, l); sAh[0][pk+1][pm] = h; sAl[0][pk+1][pm] = l;
        tf32_split(ra.z, h, l); sAh[0][pk+2][pm] = h; sAl[0][pk+2][pm] = l;
        tf32_split(ra.w, h, l); sAh[0][pk+3][pm] = h; sAl[0][pk+3][pm] = l;
        tf32_split(rb.x, h, l); sBh[0][pk+0][pm] = h; sBl[0][pk+0][pm] = l;
        tf32_split(rb.y, h, l); sBh[0][pk+1][pm] = h; sBl[0][pk+1][pm] = l;
        tf32_split(rb.z, h, l); sBh[0][pk+2][pm] = h; sBl[0][pk+2][pm] = l;
        tf32_split(rb.w, h, l); sBh[0][pk+3][pm] = h; sBl[0][pk+3][pm] = l;
    }
    __syncthreads();

    int buf = 0;
    for (int ks = 0; ks < 240; ks++) {
        float4 na, nb;
        const bool more = (ks < 239);
        if (more) {
            na = __ldg((const float4*)(Ag + (ks + 1) * 8));
            nb = __ldg((const float4*)(Bg + (ks + 1) * 8));
        }

        // --- compute on buf ---
        unsigned ah[2][4], al[2][4];
        #pragma unroll
        for (int mt = 0; mt < 2; mt++) {
            int r0 = wm * 32 + mt * 16 + gid;
            ah[mt][0] = sAh[buf][tig    ][r0];
            ah[mt][1] = sAh[buf][tig    ][r0 + 8];
            ah[mt][2] = sAh[buf][tig + 4][r0];
            ah[mt][3] = sAh[buf][tig + 4][r0 + 8];
            al[mt][0] = sAl[buf][tig    ][r0];
            al[mt][1] = sAl[buf][tig    ][r0 + 8];
            al[mt][2] = sAl[buf][tig + 4][r0];
            al[mt][3] = sAl[buf][tig + 4][r0 + 8];
        }
        #pragma unroll
        for (int nt = 0; nt < 8; nt++) {
            int cb = wn * 64 + nt * 8 + gid;
            unsigned bh0 = sBh[buf][tig    ][cb];
            unsigned bh1 = sBh[buf][tig + 4][cb];
            unsigned bl0 = sBl[buf][tig    ][cb];
            unsigned bl1 = sBl[buf][tig + 4][cb];
            #pragma unroll
            for (int mt = 0; mt < 2; mt++) {
                MMA_TF32(c[mt][nt], ah[mt], bh0, bh1);
                MMA_TF32(c[mt][nt], ah[mt], bl0, bl1);
                MMA_TF32(c[mt][nt], al[mt], bh0, bh1);
            }
        }

        // --- fill next buffer ---
        if (more) {
            int nx = buf ^ 1;
            unsigned h, l;
            tf32_split(na.x, h, l); sAh[nx][pk+0][pm] = h; sAl[nx][pk+0][pm] = l;
            tf32_split(na.y, h, l); sAh[nx][pk+1][pm] = h; sAl[nx][pk+1][pm] = l;
            tf32_split(na.z, h, l); sAh[nx][pk+2][pm] = h; sAl[nx][pk+2][pm] = l;
            tf32_split(na.w, h, l); sAh[nx][pk+3][pm] = h; sAl[nx][pk+3][pm] = l;
            tf32_split(nb.x, h, l); sBh[nx][pk+0][pm] = h; sBl[nx][pk+0][pm] = l;
            tf32_split(nb.y, h, l); sBh[nx][pk+1][pm] = h; sBl[nx][pk+1][pm] = l;
            tf32_split(nb.z, h, l); sBh[nx][pk+2][pm] = h; sBl[nx][pk+2][pm] = l;
            tf32_split(nb.w, h, l); sBh[nx][pk+3][pm] = h; sBl[nx][pk+3][pm] = l;
        }
        __syncthreads();
        buf ^= 1;
    }

    // epilogue: c[mt][nt][q] -> g_xproj + bias
    #pragma unroll
    for (int mt = 0; mt < 2; mt++) {
        int r0 = m0 + wm * 32 + mt * 16 + gid;
        #pragma unroll
        for (int nt = 0; nt < 8; nt++) {
            int col = n0 + wn * 64 + nt * 8 + 2 * tig;
            float b0 = __ldg(bias + col), b1 = __ldg(bias + col + 1);
            float2 v0 = make_float2(c[mt][nt][0] + b0, c[mt][nt][1] + b1);
            float2 v1 = make_float2(c[mt][nt][2] + b0, c[mt][nt][3] + b1);
            *(float2*)(g_xproj + (size_t)r0 * 5760 + col) = v0;
            *(float2*)(g_xproj + (size_t)(r0 + 8) * 5760 + col) = v1;
        }
    }
}

// ---------------- convert w_hh fp32 -> fp16, regrouped [unit][gate][k] -----
__global__ void convert_whh(const float* __restrict__ Whh) {
    const int row = blockIdx.x;              // 0..5759 = gate*1920 + unit
    const int gate = row / 1920, unit = row % 1920;
    const float* src = Whh + (size_t)row * 1920;
    __half* dst = g_whh_h + ((size_t)unit * 3 + gate) * 1920;
    for (int k = threadIdx.x; k < 1920; k += 256)
        dst[k] = __float2half(src[k]);
}

// ---------------- init: zero tags, publish h0 (tag=1) ----------------------
__global__ void init_kernel(const float* __restrict__ h0) {
    const int total = (NF + 1) * 960;
    uint4* base = &g_msg[0][0];
    for (int i = blockIdx.x * blockDim.x + threadIdx.x; i < total;
         i += gridDim.x * blockDim.x) {
        uint4 v;
        if (i < 960) {
            v.x = 1u; v.y = 0u;
            v.z = __float_as_uint(h0[2 * i]);
            v.w = __float_as_uint(h0[2 * i + 1]);
        } else {
            v.x = 0u; v.y = 0u; v.z = 0u; v.w = 0u;
        }
        st_cg_u4(base + i, v);
    }
}

// ---------------- persistent GRU scan: packed-message dataflow (R6) --------
// 120 CTAs x 512 thr; CTA owns 16 hidden units (8 messages), warp w -> unit.
#define W_HALVES (16 * 3 * 1920)
#define GRU_SMEM (W_HALVES * 2 + 1920 * 4)

__global__ void __launch_bounds__(512) gru_kernel(const float* __restrict__ bhh) {
    extern __shared__ __align__(16) char smraw[];
    __half* sw = (__half*)smraw;
    float* sh = (float*)(smraw + W_HALVES * 2);
    __shared__ float s_new[16];
    const int tid = threadIdx.x;
    const int cta = blockIdx.x;

    {
        const uint4* src = (const uint4*)(g_whh_h + (size_t)cta * W_HALVES);
        uint4* dst = (uint4*)sw;
        for (int i = tid; i < W_HALVES / 8; i += 512) dst[i] = src[i];
    }
    const int ul = tid >> 5, lane = tid & 31;
    const int wi = cta * 16 + ul;
    const __half2* wr2 = (const __half2*)(sw + ul * 3 * 1920);
    const __half2* wz2 = wr2 + 960;
    const __half2* wn2 = wz2 + 960;
    const float br = bhh[wi], bz = bhh[1920 + wi], bn = bhh[3840 + wi];
    const bool has2 = (tid < 448);
    __syncthreads();

    for (int t = 0; t < 2048; t++) {
        const unsigned want = (unsigned)(t + 1);
        // one-load detect+data: poll my two unit-pair messages, interleaved
        {
            uint4 v0, v1;
            bool d0 = false, d1 = !has2;
            do {
                if (!d0) { v0 = ld_cg_u4(&g_msg[t][tid]);       d0 = (v0.x == want); }
                if (!d1) { v1 = ld_cg_u4(&g_msg[t][tid + 512]); d1 = (v1.x == want); }
                if (!(d0 && d1)) __nanosleep(30);
            } while (!(d0 && d1));
            sh[2 * tid]     = __uint_as_float(v0.z);
            sh[2 * tid + 1] = __uint_as_float(v0.w);
            if (has2) {
                sh[2 * (tid + 512)]     = __uint_as_float(v1.z);
                sh[2 * (tid + 512) + 1] = __uint_as_float(v1.w);
            }
        }

        // prefetch this step's x-projection (lane 0 only uses it)
        float xr = 0.f, xz = 0.f, xn = 0.f;
        if (lane == 0) {
            const float* xp = g_xproj + (size_t)t * 5760;
            xr = __ldg(xp + wi); xz = __ldg(xp + 1920 + wi); xn = __ldg(xp + 3840 + wi);
        }
        __syncthreads();
        const float2* sh2 = (const float2*)sh;

        float sr = 0.f, sz = 0.f, sn = 0.f;
        #pragma unroll 6
        for (int it = 0; it < 30; it++) {
            const int idx = it * 32 + lane;
            float2 h2 = sh2[idx];
            float2 a = __half22float2(wr2[idx]);
            float2 b = __half22float2(wz2[idx]);
            float2 c = __half22float2(wn2[idx]);
            sr = fmaf(h2.y, a.y, fmaf(h2.x, a.x, sr));
            sz = fmaf(h2.y, b.y, fmaf(h2.x, b.x, sz));
            sn = fmaf(h2.y, c.y, fmaf(h2.x, c.x, sn));
        }
        #pragma unroll
        for (int off = 16; off > 0; off >>= 1) {
            sr += __shfl_xor_sync(0xffffffffu, sr, off);
            sz += __shfl_xor_sync(0xffffffffu, sz, off);
            sn += __shfl_xor_sync(0xffffffffu, sn, off);
        }
        if (lane == 0) {
            float r  = 1.f / (1.f + expf(-(xr + sr + br)));
            float z  = 1.f / (1.f + expf(-(xz + sz + bz)));
            float nn = tanhf(xn + r * (sn + bn));
            s_new[ul] = (1.f - z) * nn + z * sh[wi];
        }
        __syncthreads();
        // publish 8 packed messages for this CTA's 16 units
        if (tid < 8) {
            uint4 v;
            v.x = want + 1u; v.y = 0u;
            v.z = __float_as_uint(s_new[2 * tid]);
            v.w = __float_as_uint(s_new[2 * tid + 1]);
            st_cg_u4(&g_msg[t + 1][cta * 8 + tid], v);
        }
    }
}

// ---------------- final FC: [1,1920] x [2,1920]^T + fc_b -------------------
__global__ void fc_kernel(const float* __restrict__ fcw,
                          const float* __restrict__ fcb,
                          float* __restrict__ out) {
    __shared__ float red0[256], red1[256];
    const int tid = threadIdx.x;
    float s0 = 0.f, s1 = 0.f;
    for (int p = tid; p < 960; p += 256) {
        uint4 v = g_msg[NF][p];
        float h0v = __uint_as_float(v.z);
        float h1v = __uint_as_float(v.w);
        int k = 2 * p;
        s0 = fmaf(h0v, fcw[k], s0);     s0 = fmaf(h1v, fcw[k + 1], s0);
        s1 = fmaf(h0v, fcw[1920 + k], s1); s1 = fmaf(h1v, fcw[1920 + k + 1], s1);
    }
    red0[tid] = s0; red1[tid] = s1;
    __syncthreads();
    for (int s = 128; s > 0; s >>= 1) {
        if (tid < s) { red0[tid] += red0[tid + s]; red1[tid] += red1[tid + s]; }
        __syncthreads();
    }
    if (tid == 0) { out[0] = red0[0] + fcb[0]; out[1] = red1[0] + fcb[1]; }
}

// ---------------- launcher --------------------------------------------------
extern "C" void kernel_launch(void* const* d_in, const int* in_sizes, int n_in,
                              void* d_out, int out_size) {
    const float* x    = (const float*)d_in[0];
    const float* c1w  = (const float*)d_in[1];
    const float* c1b  = (const float*)d_in[2];
    const float* c2w  = (const float*)d_in[3];
    const float* c2b  = (const float*)d_in[4];
    const float* wih  = (const float*)d_in[5];
    const float* whh  = (const float*)d_in[6];
    const float* bih  = (const float*)d_in[7];
    const float* bhh  = (const float*)d_in[8];
    const float* fcw  = (const float*)d_in[9];
    const float* fcb  = (const float*)d_in[10];
    const float* h0   = (const float*)d_in[11];
    (void)in_sizes; (void)n_in; (void)out_size;

    cudaFuncSetAttribute(conv1_kernel, cudaFuncAttributeMaxDynamicSharedMemorySize, C1_SMEM);
    cudaFuncSetAttribute(conv2_kernel, cudaFuncAttributeMaxDynamicSharedMemorySize, C2_SMEM);
    cudaFuncSetAttribute(gru_kernel, cudaFuncAttributeMaxDynamicSharedMemorySize, GRU_SMEM);

    conv1_kernel<<<dim3(NF, 4), 256, C1_SMEM>>>(x, c1w, c1b);
    conv2_kernel<<<NF, 768, C2_SMEM>>>(c2w, c2b);
    gemm_xproj_tc<<<dim3(16, 45), 256>>>(wih, bih);
    convert_whh<<<5760, 256>>>(whh);
    init_kernel<<<512, 256>>>(h0);
    gru_kernel<<<120, 512, GRU_SMEM>>>(bhh);
    fc_kernel<<<1, 256>>>(fcw, fcb, (float*)d_out);
}